// round 3
// baseline (speedup 1.0000x reference)
#include <cuda_runtime.h>
#include <math.h>

#define B_   2
#define S_   4096
#define DM_  1024
#define H_   16
#define HD_  64
#define MROWS (B_ * S_)

__device__ float g_q[MROWS * DM_];
__device__ float g_k[MROWS * DM_];
__device__ float g_v[MROWS * DM_];
__device__ float g_attn[MROWS * DM_];

__device__ __forceinline__ unsigned f2tf(float x) {
  unsigned r;
  asm("cvt.rna.tf32.f32 %0, %1;" : "=r"(r) : "f"(x));
  return r;
}

__device__ __forceinline__ void mma_tf32(float c[4], const unsigned a[4],
                                         const unsigned b[2]) {
  asm volatile(
      "mma.sync.aligned.m16n8k8.row.col.f32.tf32.tf32.f32 "
      "{%0,%1,%2,%3}, {%4,%5,%6,%7}, {%8,%9}, {%0,%1,%2,%3};"
      : "+f"(c[0]), "+f"(c[1]), "+f"(c[2]), "+f"(c[3])
      : "r"(a[0]), "r"(a[1]), "r"(a[2]), "r"(a[3]), "r"(b[0]), "r"(b[1]));
}

__device__ __forceinline__ void cp16(void* smem_dst, const void* gmem_src) {
  unsigned s = (unsigned)__cvta_generic_to_shared(smem_dst);
  asm volatile("cp.async.cg.shared.global [%0], [%1], 16;" ::"r"(s),
               "l"(gmem_src));
}
__device__ __forceinline__ void cp_commit() {
  asm volatile("cp.async.commit_group;");
}
__device__ __forceinline__ void cp_wait1() {
  asm volatile("cp.async.wait_group 1;");
}

// ---------------------------------------------------------------------------
// GEMM: C = X @ W + bias via tf32 mma.sync. Tile 128x128x32.
// rnd!=0 -> output values rounded to tf32 (so flash can cp.async them raw).
// ---------------------------------------------------------------------------
__global__ __launch_bounds__(256) void gemm_mma_kernel(
    const float* __restrict__ X, const float* __restrict__ W,
    const float* __restrict__ bias, float* __restrict__ C, int rnd) {
  __shared__ unsigned As[128 * 36];
  __shared__ unsigned Bs[32 * 136];

  const int tid  = threadIdx.x;
  const int lane = tid & 31;
  const int wid  = tid >> 5;
  const int g    = lane >> 2;
  const int tg   = lane & 3;
  const int wm   = wid & 3;
  const int wn   = wid >> 2;
  const long m0  = (long)blockIdx.y * 128;
  const int  n0  = blockIdx.x * 128;

  float4 ra[4], rb[4];
#pragma unroll
  for (int i = 0; i < 4; i++) {
    int idx = tid + i * 256;
    ra[i] = *(const float4*)(X + (m0 + (idx >> 3)) * DM_ + ((idx & 7) << 2));
    rb[i] = *(const float4*)(W + (long)(idx >> 5) * DM_ + n0 + ((idx & 31) << 2));
  }

  float acc[2][8][4];
#pragma unroll
  for (int mt = 0; mt < 2; mt++)
#pragma unroll
    for (int nt = 0; nt < 8; nt++)
#pragma unroll
      for (int j = 0; j < 4; j++) acc[mt][nt][j] = 0.f;

  for (int k0 = 0; k0 < DM_; k0 += 32) {
    __syncthreads();
#pragma unroll
    for (int i = 0; i < 4; i++) {
      int idx = tid + i * 256;
      int r = idx >> 3, k4 = (idx & 7) << 2;
      As[r * 36 + k4 + 0] = f2tf(ra[i].x);
      As[r * 36 + k4 + 1] = f2tf(ra[i].y);
      As[r * 36 + k4 + 2] = f2tf(ra[i].z);
      As[r * 36 + k4 + 3] = f2tf(ra[i].w);
      int bk = idx >> 5, bn = (idx & 31) << 2;
      Bs[bk * 136 + bn + 0] = f2tf(rb[i].x);
      Bs[bk * 136 + bn + 1] = f2tf(rb[i].y);
      Bs[bk * 136 + bn + 2] = f2tf(rb[i].z);
      Bs[bk * 136 + bn + 3] = f2tf(rb[i].w);
    }
    __syncthreads();

    if (k0 + 32 < DM_) {
#pragma unroll
      for (int i = 0; i < 4; i++) {
        int idx = tid + i * 256;
        ra[i] = *(const float4*)(X + (m0 + (idx >> 3)) * DM_ + k0 + 32 +
                                 ((idx & 7) << 2));
        rb[i] = *(const float4*)(W + (long)(k0 + 32 + (idx >> 5)) * DM_ + n0 +
                                 ((idx & 31) << 2));
      }
    }

#pragma unroll
    for (int ks = 0; ks < 4; ks++) {
      unsigned a[2][4];
#pragma unroll
      for (int mt = 0; mt < 2; mt++) {
        int row = wm * 32 + mt * 16 + g;
        int col = ks * 8 + tg;
        a[mt][0] = As[row * 36 + col];
        a[mt][1] = As[(row + 8) * 36 + col];
        a[mt][2] = As[row * 36 + col + 4];
        a[mt][3] = As[(row + 8) * 36 + col + 4];
      }
#pragma unroll
      for (int nt = 0; nt < 8; nt++) {
        unsigned b[2];
        int n  = wn * 64 + nt * 8 + g;
        int kk = ks * 8 + tg;
        b[0] = Bs[kk * 136 + n];
        b[1] = Bs[(kk + 4) * 136 + n];
        mma_tf32(acc[0][nt], a[0], b);
        mma_tf32(acc[1][nt], a[1], b);
      }
    }
  }

#pragma unroll
  for (int mt = 0; mt < 2; mt++) {
    long row = m0 + wm * 32 + mt * 16 + g;
#pragma unroll
    for (int nt = 0; nt < 8; nt++) {
      int col = n0 + wn * 64 + nt * 8 + 2 * tg;
      float2 bb = *(const float2*)(bias + col);
      float v00 = acc[mt][nt][0] + bb.x, v01 = acc[mt][nt][1] + bb.y;
      float v10 = acc[mt][nt][2] + bb.x, v11 = acc[mt][nt][3] + bb.y;
      if (rnd) {
        v00 = __uint_as_float(f2tf(v00));
        v01 = __uint_as_float(f2tf(v01));
        v10 = __uint_as_float(f2tf(v10));
        v11 = __uint_as_float(f2tf(v11));
      }
      *(float2*)(C + row * DM_ + col)       = make_float2(v00, v01);
      *(float2*)(C + (row + 8) * DM_ + col) = make_float2(v10, v11);
    }
  }
}

// Fused QKV: grid.z selects which projection.
__global__ __launch_bounds__(256) void gemm_qkv_kernel(
    const float* __restrict__ X, const float* __restrict__ Wq,
    const float* __restrict__ Wk, const float* __restrict__ Wv,
    const float* __restrict__ bq, const float* __restrict__ bk,
    const float* __restrict__ bv, float* __restrict__ Q,
    float* __restrict__ Ko, float* __restrict__ Vo);

// ---------------------------------------------------------------------------
// Flash attention, tf32 mma, 2 CTAs/SM.
// CTA: 128 q rows, 8 warps x 16 rows. KV blocks of 64, cp.async double-buffer
// (K/V are pre-rounded to tf32 by the projection GEMM, so raw copy is exact).
// Smem words: Ks 2*64*68, Vs 2*64*72, Ps 128*72  -> 108544 B
// ---------------------------------------------------------------------------
__global__ __launch_bounds__(256, 2) void flash_tc_kernel(
    const float* __restrict__ Qg, const float* __restrict__ Kg,
    const float* __restrict__ Vg, float* __restrict__ Og) {
  extern __shared__ unsigned sm[];
  unsigned* Ks = sm;                 // 2 * 4352
  unsigned* Vs = sm + 2 * 4352;      // 2 * 4608
  unsigned* Ps = sm + 2 * 4352 + 2 * 4608;  // 128*72

  const int tid  = threadIdx.x;
  const int lane = tid & 31;
  const int wid  = tid >> 5;
  const int g    = lane >> 2;
  const int tg   = lane & 3;
  const int bh   = blockIdx.y;
  const int b    = bh >> 4;
  const int h    = bh & 15;
  const int q0   = blockIdx.x * 128;

  const float* Qb  = Qg + ((long)(b * S_ + q0)) * DM_ + h * HD_;
  const float* Kb0 = Kg + ((long)b * S_) * DM_ + h * HD_;
  const float* Vb0 = Vg + ((long)b * S_) * DM_ + h * HD_;
  float* Ob        = Og + ((long)(b * S_ + q0)) * DM_ + h * HD_;

  // softmax in exp2 domain: scale = 1/sqrt(64) * log2(e)
  const float QSCALE = 0.18033688011112042592f;

  // stage K/V block kb into buffer p via cp.async (one 16B chunk x4 per thread)
  auto stage = [&](int kb, int p) {
    const float* Kb = Kb0 + (long)(kb * 64) * DM_;
    const float* Vb = Vb0 + (long)(kb * 64) * DM_;
    unsigned* KsD = Ks + p * 4352;
    unsigned* VsD = Vs + p * 4608;
#pragma unroll
    for (int i = 0; i < 4; i++) {
      int idx = tid + i * 256;
      int kv = idx >> 4, d4 = (idx & 15) << 2;
      cp16(KsD + kv * 68 + d4, Kb + (long)kv * DM_ + d4);
      cp16(VsD + kv * 72 + d4, Vb + (long)kv * DM_ + d4);
    }
    cp_commit();
  };

  // Q A-fragments (registers, whole KV loop)
  unsigned qa[8][4];
  {
    int qrow = wid * 16 + g;
#pragma unroll
    for (int ks = 0; ks < 8; ks++) {
      int c = ks * 8 + tg;
      qa[ks][0] = f2tf(QSCALE * Qb[(long)qrow * DM_ + c]);
      qa[ks][1] = f2tf(QSCALE * Qb[(long)(qrow + 8) * DM_ + c]);
      qa[ks][2] = f2tf(QSCALE * Qb[(long)qrow * DM_ + c + 4]);
      qa[ks][3] = f2tf(QSCALE * Qb[(long)(qrow + 8) * DM_ + c + 4]);
    }
  }

  float oacc[8][4];
#pragma unroll
  for (int nt = 0; nt < 8; nt++)
#pragma unroll
    for (int j = 0; j < 4; j++) oacc[nt][j] = 0.f;
  float m0r = -INFINITY, m1r = -INFINITY, l0 = 0.f, l1 = 0.f;

  stage(0, 0);
  stage(1, 1);

  for (int kb = 0; kb < S_ / 64; kb++) {
    const int p = kb & 1;
    cp_wait1();
    __syncthreads();
    const unsigned* KsP = Ks + p * 4352;
    const unsigned* VsP = Vs + p * 4608;

    // ---- S = Q K^T ----
    float sacc[8][4];
#pragma unroll
    for (int nt = 0; nt < 8; nt++)
#pragma unroll
      for (int j = 0; j < 4; j++) sacc[nt][j] = 0.f;
#pragma unroll
    for (int nt = 0; nt < 8; nt++) {
#pragma unroll
      for (int ks = 0; ks < 8; ks++) {
        unsigned bf[2];
        int n  = nt * 8 + g;
        int kk = ks * 8 + tg;
        bf[0] = KsP[n * 68 + kk];
        bf[1] = KsP[n * 68 + kk + 4];
        mma_tf32(sacc[nt], qa[ks], bf);
      }
    }

    // ---- online softmax (exp2 domain) ----
    float mx0 = -INFINITY, mx1 = -INFINITY;
#pragma unroll
    for (int nt = 0; nt < 8; nt++) {
      mx0 = fmaxf(mx0, fmaxf(sacc[nt][0], sacc[nt][1]));
      mx1 = fmaxf(mx1, fmaxf(sacc[nt][2], sacc[nt][3]));
    }
#pragma unroll
    for (int off = 1; off <= 2; off <<= 1) {
      mx0 = fmaxf(mx0, __shfl_xor_sync(0xffffffffu, mx0, off));
      mx1 = fmaxf(mx1, __shfl_xor_sync(0xffffffffu, mx1, off));
    }
    float mn0 = fmaxf(m0r, mx0), mn1 = fmaxf(m1r, mx1);
    float al0 = exp2f(m0r - mn0), al1 = exp2f(m1r - mn1);
    m0r = mn0; m1r = mn1;

    float ps0 = 0.f, ps1 = 0.f;
#pragma unroll
    for (int nt = 0; nt < 8; nt++) {
      sacc[nt][0] = exp2f(sacc[nt][0] - mn0);
      sacc[nt][1] = exp2f(sacc[nt][1] - mn0);
      sacc[nt][2] = exp2f(sacc[nt][2] - mn1);
      sacc[nt][3] = exp2f(sacc[nt][3] - mn1);
      ps0 += sacc[nt][0] + sacc[nt][1];
      ps1 += sacc[nt][2] + sacc[nt][3];
    }
#pragma unroll
    for (int off = 1; off <= 2; off <<= 1) {
      ps0 += __shfl_xor_sync(0xffffffffu, ps0, off);
      ps1 += __shfl_xor_sync(0xffffffffu, ps1, off);
    }
    l0 = l0 * al0 + ps0;
    l1 = l1 * al1 + ps1;
#pragma unroll
    for (int nt = 0; nt < 8; nt++) {
      oacc[nt][0] *= al0;
      oacc[nt][1] *= al0;
      oacc[nt][2] *= al1;
      oacc[nt][3] *= al1;
    }

    // ---- store P (tf32, STS.64, conflict-free with stride 72) ----
    {
      int pr = wid * 16 + g;
#pragma unroll
      for (int nt = 0; nt < 8; nt++) {
        int col = nt * 8 + 2 * tg;
        uint2 lo = make_uint2(f2tf(sacc[nt][0]), f2tf(sacc[nt][1]));
        uint2 hi = make_uint2(f2tf(sacc[nt][2]), f2tf(sacc[nt][3]));
        *(uint2*)(Ps + pr * 72 + col)       = lo;
        *(uint2*)(Ps + (pr + 8) * 72 + col) = hi;
      }
    }
    __syncwarp();

    // ---- O += P V ----
#pragma unroll
    for (int ks = 0; ks < 8; ks++) {
      unsigned pa[4];
      int pr  = wid * 16 + g;
      int col = ks * 8 + tg;
      pa[0] = Ps[pr * 72 + col];
      pa[1] = Ps[(pr + 8) * 72 + col];
      pa[2] = Ps[pr * 72 + col + 4];
      pa[3] = Ps[(pr + 8) * 72 + col + 4];
#pragma unroll
      for (int nt = 0; nt < 8; nt++) {
        unsigned bf[2];
        int n  = nt * 8 + g;
        int kk = ks * 8 + tg;
        bf[0] = VsP[kk * 72 + n];
        bf[1] = VsP[(kk + 4) * 72 + n];
        mma_tf32(oacc[nt], pa, bf);
      }
    }

    __syncthreads();
    if (kb + 2 < S_ / 64) {
      stage(kb + 2, p);
    } else {
      cp_commit();  // keep group accounting consistent
    }
  }

  float inv0 = 1.f / l0, inv1 = 1.f / l1;
  int row = wid * 16 + g;
#pragma unroll
  for (int nt = 0; nt < 8; nt++) {
    int col = nt * 8 + 2 * tg;
    float2 o0 = make_float2(oacc[nt][0] * inv0, oacc[nt][1] * inv0);
    float2 o1 = make_float2(oacc[nt][2] * inv1, oacc[nt][3] * inv1);
    *(float2*)(Ob + (long)row * DM_ + col)       = o0;
    *(float2*)(Ob + (long)(row + 8) * DM_ + col) = o1;
  }
}

// Fused QKV wrapper (defined after gemm_mma_kernel so it can call the body
// via simple dispatch — implemented as its own kernel to keep one launch).
__global__ __launch_bounds__(256) void gemm_qkv_dispatch(
    const float* __restrict__ X, const float* __restrict__ Wq,
    const float* __restrict__ Wk, const float* __restrict__ Wv,
    const float* __restrict__ bq, const float* __restrict__ bk,
    const float* __restrict__ bv, float* __restrict__ Qo,
    float* __restrict__ Ko, float* __restrict__ Vo) {
  // Replicate gemm body with per-z operand selection.
  const float* W = (blockIdx.z == 0) ? Wq : (blockIdx.z == 1) ? Wk : Wv;
  const float* bias = (blockIdx.z == 0) ? bq : (blockIdx.z == 1) ? bk : bv;
  float* C = (blockIdx.z == 0) ? Qo : (blockIdx.z == 1) ? Ko : Vo;

  __shared__ unsigned As[128 * 36];
  __shared__ unsigned Bs[32 * 136];

  const int tid  = threadIdx.x;
  const int lane = tid & 31;
  const int wid  = tid >> 5;
  const int g    = lane >> 2;
  const int tg   = lane & 3;
  const int wm   = wid & 3;
  const int wn   = wid >> 2;
  const long m0  = (long)blockIdx.y * 128;
  const int  n0  = blockIdx.x * 128;

  float4 ra[4], rb[4];
#pragma unroll
  for (int i = 0; i < 4; i++) {
    int idx = tid + i * 256;
    ra[i] = *(const float4*)(X + (m0 + (idx >> 3)) * DM_ + ((idx & 7) << 2));
    rb[i] = *(const float4*)(W + (long)(idx >> 5) * DM_ + n0 + ((idx & 31) << 2));
  }

  float acc[2][8][4];
#pragma unroll
  for (int mt = 0; mt < 2; mt++)
#pragma unroll
    for (int nt = 0; nt < 8; nt++)
#pragma unroll
      for (int j = 0; j < 4; j++) acc[mt][nt][j] = 0.f;

  for (int k0 = 0; k0 < DM_; k0 += 32) {
    __syncthreads();
#pragma unroll
    for (int i = 0; i < 4; i++) {
      int idx = tid + i * 256;
      int r = idx >> 3, k4 = (idx & 7) << 2;
      As[r * 36 + k4 + 0] = f2tf(ra[i].x);
      As[r * 36 + k4 + 1] = f2tf(ra[i].y);
      As[r * 36 + k4 + 2] = f2tf(ra[i].z);
      As[r * 36 + k4 + 3] = f2tf(ra[i].w);
      int bk = idx >> 5, bn = (idx & 31) << 2;
      Bs[bk * 136 + bn + 0] = f2tf(rb[i].x);
      Bs[bk * 136 + bn + 1] = f2tf(rb[i].y);
      Bs[bk * 136 + bn + 2] = f2tf(rb[i].z);
      Bs[bk * 136 + bn + 3] = f2tf(rb[i].w);
    }
    __syncthreads();

    if (k0 + 32 < DM_) {
#pragma unroll
      for (int i = 0; i < 4; i++) {
        int idx = tid + i * 256;
        ra[i] = *(const float4*)(X + (m0 + (idx >> 3)) * DM_ + k0 + 32 +
                                 ((idx & 7) << 2));
        rb[i] = *(const float4*)(W + (long)(k0 + 32 + (idx >> 5)) * DM_ + n0 +
                                 ((idx & 31) << 2));
      }
    }

#pragma unroll
    for (int ks = 0; ks < 4; ks++) {
      unsigned a[2][4];
#pragma unroll
      for (int mt = 0; mt < 2; mt++) {
        int row = wm * 32 + mt * 16 + g;
        int col = ks * 8 + tg;
        a[mt][0] = As[row * 36 + col];
        a[mt][1] = As[(row + 8) * 36 + col];
        a[mt][2] = As[row * 36 + col + 4];
        a[mt][3] = As[(row + 8) * 36 + col + 4];
      }
#pragma unroll
      for (int nt = 0; nt < 8; nt++) {
        unsigned b[2];
        int n  = wn * 64 + nt * 8 + g;
        int kk = ks * 8 + tg;
        b[0] = Bs[kk * 136 + n];
        b[1] = Bs[(kk + 4) * 136 + n];
        mma_tf32(acc[0][nt], a[0], b);
        mma_tf32(acc[1][nt], a[1], b);
      }
    }
  }

#pragma unroll
  for (int mt = 0; mt < 2; mt++) {
    long row = m0 + wm * 32 + mt * 16 + g;
#pragma unroll
    for (int nt = 0; nt < 8; nt++) {
      int col = n0 + wn * 64 + nt * 8 + 2 * tg;
      float2 bb = *(const float2*)(bias + col);
      // pre-round outputs to tf32 so flash can cp.async them bit-exactly
      float2 o0 = make_float2(
          __uint_as_float(f2tf(acc[mt][nt][0] + bb.x)),
          __uint_as_float(f2tf(acc[mt][nt][1] + bb.y)));
      float2 o1 = make_float2(
          __uint_as_float(f2tf(acc[mt][nt][2] + bb.x)),
          __uint_as_float(f2tf(acc[mt][nt][3] + bb.y)));
      *(float2*)(C + row * DM_ + col)       = o0;
      *(float2*)(C + (row + 8) * DM_ + col) = o1;
    }
  }
}

// ---------------------------------------------------------------------------
extern "C" void kernel_launch(void* const* d_in, const int* in_sizes, int n_in,
                              void* d_out, int out_size) {
  const float* x  = (const float*)d_in[0];
  const float* Wq = (const float*)d_in[1];
  const float* bq = (const float*)d_in[2];
  const float* Wk = (const float*)d_in[3];
  const float* bk = (const float*)d_in[4];
  const float* Wv = (const float*)d_in[5];
  const float* bv = (const float*)d_in[6];
  const float* Wo = (const float*)d_in[7];
  const float* bo = (const float*)d_in[8];
  float* out = (float*)d_out;

  float *q, *k, *v, *attn;
  cudaGetSymbolAddress((void**)&q, g_q);
  cudaGetSymbolAddress((void**)&k, g_k);
  cudaGetSymbolAddress((void**)&v, g_v);
  cudaGetSymbolAddress((void**)&attn, g_attn);

  dim3 qkvgrid(DM_ / 128, MROWS / 128, 3);
  gemm_qkv_dispatch<<<qkvgrid, 256>>>(x, Wq, Wk, Wv, bq, bk, bv, q, k, v);

  const int flash_smem = (2 * 4352 + 2 * 4608 + 128 * 72) * (int)sizeof(unsigned);
  cudaFuncSetAttribute(flash_tc_kernel,
                       cudaFuncAttributeMaxDynamicSharedMemorySize, flash_smem);
  flash_tc_kernel<<<dim3(S_ / 128, B_ * H_), 256, flash_smem>>>(q, k, v, attn);

  dim3 ggrid(DM_ / 128, MROWS / 128);
  gemm_mma_kernel<<<ggrid, 256>>>(attn, Wo, bo, out, 0);
}

// round 4
// speedup vs baseline: 1.4991x; 1.4991x over previous
#include <cuda_runtime.h>
#include <math.h>

#define B_   2
#define S_   4096
#define DM_  1024
#define H_   16
#define HD_  64
#define MROWS (B_ * S_)

__device__ float g_q[MROWS * DM_];
__device__ float g_k[MROWS * DM_];
__device__ float g_v[MROWS * DM_];
__device__ float g_attn[MROWS * DM_];
__device__ float g_xt[MROWS * DM_];
__device__ float g_wq[DM_ * DM_];
__device__ float g_wk[DM_ * DM_];
__device__ float g_wv[DM_ * DM_];
__device__ float g_wo[DM_ * DM_];

__device__ __forceinline__ unsigned f2tf(float x) {
  unsigned r;
  asm("cvt.rna.tf32.f32 %0, %1;" : "=r"(r) : "f"(x));
  return r;
}

__device__ __forceinline__ void mma_tf32(float c[4], const unsigned a[4],
                                         const unsigned b[2]) {
  asm volatile(
      "mma.sync.aligned.m16n8k8.row.col.f32.tf32.tf32.f32 "
      "{%0,%1,%2,%3}, {%4,%5,%6,%7}, {%8,%9}, {%0,%1,%2,%3};"
      : "+f"(c[0]), "+f"(c[1]), "+f"(c[2]), "+f"(c[3])
      : "r"(a[0]), "r"(a[1]), "r"(a[2]), "r"(a[3]), "r"(b[0]), "r"(b[1]));
}

__device__ __forceinline__ void cp16(void* smem_dst, const void* gmem_src) {
  unsigned s = (unsigned)__cvta_generic_to_shared(smem_dst);
  asm volatile("cp.async.cg.shared.global [%0], [%1], 16;" ::"r"(s),
               "l"(gmem_src));
}
__device__ __forceinline__ void cp_commit() {
  asm volatile("cp.async.commit_group;");
}
__device__ __forceinline__ void cp_wait1() {
  asm volatile("cp.async.wait_group 1;");
}

// ---------------------------------------------------------------------------
// Elementwise tf32 rounding pre-pass (inputs already tf32 -> GEMMs cp.async raw)
// ---------------------------------------------------------------------------
__global__ void tf32_round_kernel(const float* __restrict__ in,
                                  float* __restrict__ out, long n4) {
  long i = (long)blockIdx.x * blockDim.x + threadIdx.x;
  long stride = (long)gridDim.x * blockDim.x;
  for (; i < n4; i += stride) {
    float4 v = ((const float4*)in)[i];
    v.x = __uint_as_float(f2tf(v.x));
    v.y = __uint_as_float(f2tf(v.y));
    v.z = __uint_as_float(f2tf(v.z));
    v.w = __uint_as_float(f2tf(v.w));
    ((float4*)out)[i] = v;
  }
}

// ---------------------------------------------------------------------------
// GEMM: C = A @ W + bias, tf32 mma. A,W already tf32-rounded -> raw cp.async.
// Tile 128x128x32, double-buffered smem, 256 threads, 2 CTAs/SM.
// ---------------------------------------------------------------------------
__global__ __launch_bounds__(256) void gemm_tc_kernel(
    const float* __restrict__ A, const float* __restrict__ W,
    const float* __restrict__ bias, float* __restrict__ C, int rnd) {
  __shared__ unsigned As[2][128 * 36];
  __shared__ unsigned Bs[2][32 * 136];

  const int tid  = threadIdx.x;
  const int lane = tid & 31;
  const int wid  = tid >> 5;
  const int g    = lane >> 2;
  const int tg   = lane & 3;
  const int wm   = wid & 3;
  const int wn   = wid >> 2;
  const long m0  = (long)blockIdx.y * 128;
  const int  n0  = blockIdx.x * 128;

  auto stage = [&](int k0, int buf) {
#pragma unroll
    for (int i = 0; i < 4; i++) {
      int c = tid + i * 256;
      int r = c >> 3, k4 = (c & 7) << 2;
      cp16(&As[buf][r * 36 + k4], A + (m0 + r) * DM_ + k0 + k4);
      int bk = c >> 5, bn = (c & 31) << 2;
      cp16(&Bs[buf][bk * 136 + bn], W + (long)(k0 + bk) * DM_ + n0 + bn);
    }
    cp_commit();
  };

  float acc[2][8][4];
#pragma unroll
  for (int mt = 0; mt < 2; mt++)
#pragma unroll
    for (int nt = 0; nt < 8; nt++)
#pragma unroll
      for (int j = 0; j < 4; j++) acc[mt][nt][j] = 0.f;

  stage(0, 0);
  stage(32, 1);

  const int NT = DM_ / 32;
  for (int kt = 0; kt < NT; kt++) {
    const int buf = kt & 1;
    cp_wait1();
    __syncthreads();

#pragma unroll
    for (int ks = 0; ks < 4; ks++) {
      unsigned a[2][4];
#pragma unroll
      for (int mt = 0; mt < 2; mt++) {
        int row = wm * 32 + mt * 16 + g;
        int col = ks * 8 + tg;
        a[mt][0] = As[buf][row * 36 + col];
        a[mt][1] = As[buf][(row + 8) * 36 + col];
        a[mt][2] = As[buf][row * 36 + col + 4];
        a[mt][3] = As[buf][(row + 8) * 36 + col + 4];
      }
#pragma unroll
      for (int nt = 0; nt < 8; nt++) {
        unsigned b[2];
        int n  = wn * 64 + nt * 8 + g;
        int kk = ks * 8 + tg;
        b[0] = Bs[buf][kk * 136 + n];
        b[1] = Bs[buf][(kk + 4) * 136 + n];
        mma_tf32(acc[0][nt], a[0], b);
        mma_tf32(acc[1][nt], a[1], b);
      }
    }

    __syncthreads();
    if (kt + 2 < NT) stage((kt + 2) * 32, buf);
    else cp_commit();
  }

#pragma unroll
  for (int mt = 0; mt < 2; mt++) {
    long row = m0 + wm * 32 + mt * 16 + g;
#pragma unroll
    for (int nt = 0; nt < 8; nt++) {
      int col = n0 + wn * 64 + nt * 8 + 2 * tg;
      float2 bb = *(const float2*)(bias + col);
      float v00 = acc[mt][nt][0] + bb.x, v01 = acc[mt][nt][1] + bb.y;
      float v10 = acc[mt][nt][2] + bb.x, v11 = acc[mt][nt][3] + bb.y;
      if (rnd) {
        v00 = __uint_as_float(f2tf(v00));
        v01 = __uint_as_float(f2tf(v01));
        v10 = __uint_as_float(f2tf(v10));
        v11 = __uint_as_float(f2tf(v11));
      }
      *(float2*)(C + row * DM_ + col)       = make_float2(v00, v01);
      *(float2*)(C + (row + 8) * DM_ + col) = make_float2(v10, v11);
    }
  }
}

// QKV fused via grid.z
__global__ __launch_bounds__(256) void gemm_qkv_kernel(
    const float* __restrict__ A, const float* __restrict__ Wq,
    const float* __restrict__ Wk, const float* __restrict__ Wv,
    const float* __restrict__ bq, const float* __restrict__ bk,
    const float* __restrict__ bv, float* __restrict__ Qo,
    float* __restrict__ Ko, float* __restrict__ Vo) {
  const float* W = (blockIdx.z == 0) ? Wq : (blockIdx.z == 1) ? Wk : Wv;
  const float* bias = (blockIdx.z == 0) ? bq : (blockIdx.z == 1) ? bk : bv;
  float* C = (blockIdx.z == 0) ? Qo : (blockIdx.z == 1) ? Ko : Vo;

  __shared__ unsigned As[2][128 * 36];
  __shared__ unsigned Bs[2][32 * 136];

  const int tid  = threadIdx.x;
  const int lane = tid & 31;
  const int wid  = tid >> 5;
  const int g    = lane >> 2;
  const int tg   = lane & 3;
  const int wm   = wid & 3;
  const int wn   = wid >> 2;
  const long m0  = (long)blockIdx.y * 128;
  const int  n0  = blockIdx.x * 128;

  auto stage = [&](int k0, int buf) {
#pragma unroll
    for (int i = 0; i < 4; i++) {
      int c = tid + i * 256;
      int r = c >> 3, k4 = (c & 7) << 2;
      cp16(&As[buf][r * 36 + k4], A + (m0 + r) * DM_ + k0 + k4);
      int bk = c >> 5, bn = (c & 31) << 2;
      cp16(&Bs[buf][bk * 136 + bn], W + (long)(k0 + bk) * DM_ + n0 + bn);
    }
    cp_commit();
  };

  float acc[2][8][4];
#pragma unroll
  for (int mt = 0; mt < 2; mt++)
#pragma unroll
    for (int nt = 0; nt < 8; nt++)
#pragma unroll
      for (int j = 0; j < 4; j++) acc[mt][nt][j] = 0.f;

  stage(0, 0);
  stage(32, 1);

  const int NT = DM_ / 32;
  for (int kt = 0; kt < NT; kt++) {
    const int buf = kt & 1;
    cp_wait1();
    __syncthreads();

#pragma unroll
    for (int ks = 0; ks < 4; ks++) {
      unsigned a[2][4];
#pragma unroll
      for (int mt = 0; mt < 2; mt++) {
        int row = wm * 32 + mt * 16 + g;
        int col = ks * 8 + tg;
        a[mt][0] = As[buf][row * 36 + col];
        a[mt][1] = As[buf][(row + 8) * 36 + col];
        a[mt][2] = As[buf][row * 36 + col + 4];
        a[mt][3] = As[buf][(row + 8) * 36 + col + 4];
      }
#pragma unroll
      for (int nt = 0; nt < 8; nt++) {
        unsigned b[2];
        int n  = wn * 64 + nt * 8 + g;
        int kk = ks * 8 + tg;
        b[0] = Bs[buf][kk * 136 + n];
        b[1] = Bs[buf][(kk + 4) * 136 + n];
        mma_tf32(acc[0][nt], a[0], b);
        mma_tf32(acc[1][nt], a[1], b);
      }
    }

    __syncthreads();
    if (kt + 2 < NT) stage((kt + 2) * 32, buf);
    else cp_commit();
  }

#pragma unroll
  for (int mt = 0; mt < 2; mt++) {
    long row = m0 + wm * 32 + mt * 16 + g;
#pragma unroll
    for (int nt = 0; nt < 8; nt++) {
      int col = n0 + wn * 64 + nt * 8 + 2 * tg;
      float2 bb = *(const float2*)(bias + col);
      // pre-round so flash can cp.async q/k/v raw
      float2 o0 = make_float2(__uint_as_float(f2tf(acc[mt][nt][0] + bb.x)),
                              __uint_as_float(f2tf(acc[mt][nt][1] + bb.y)));
      float2 o1 = make_float2(__uint_as_float(f2tf(acc[mt][nt][2] + bb.x)),
                              __uint_as_float(f2tf(acc[mt][nt][3] + bb.y)));
      *(float2*)(C + row * DM_ + col)       = o0;
      *(float2*)(C + (row + 8) * DM_ + col) = o1;
    }
  }
}

// ---------------------------------------------------------------------------
// Flash attention, tf32 mma. CTA: 128 threads (4 warps), 64 q rows.
// 2 CTAs/SM (smem 89KB, natural regs ~150, no forced cap).
// Smem words: Ks 2*64*68, Vs 2*64*72, Ps 64*68  -> 89088 B
// ---------------------------------------------------------------------------
__global__ __launch_bounds__(128) void flash_tc_kernel(
    const float* __restrict__ Qg, const float* __restrict__ Kg,
    const float* __restrict__ Vg, float* __restrict__ Og) {
  extern __shared__ unsigned sm[];
  unsigned* Ks = sm;                        // 2 * 4352
  unsigned* Vs = sm + 2 * 4352;             // 2 * 4608
  unsigned* Ps = sm + 2 * 4352 + 2 * 4608;  // 64*68

  const int tid  = threadIdx.x;
  const int lane = tid & 31;
  const int wid  = tid >> 5;   // 0..3
  const int g    = lane >> 2;
  const int tg   = lane & 3;
  const int bh   = blockIdx.y;
  const int b    = bh >> 4;
  const int h    = bh & 15;
  const int q0   = blockIdx.x * 64;

  const float* Qb  = Qg + ((long)(b * S_ + q0)) * DM_ + h * HD_;
  const float* Kb0 = Kg + ((long)b * S_) * DM_ + h * HD_;
  const float* Vb0 = Vg + ((long)b * S_) * DM_ + h * HD_;
  float* Ob        = Og + ((long)(b * S_ + q0)) * DM_ + h * HD_;

  // softmax in exp2 domain: 1/sqrt(64) * log2(e)
  const float QSCALE = 0.18033688011112042592f;

  auto stage = [&](int kb, int p) {
    const float* Kb = Kb0 + (long)(kb * 64) * DM_;
    const float* Vb = Vb0 + (long)(kb * 64) * DM_;
    unsigned* KsD = Ks + p * 4352;
    unsigned* VsD = Vs + p * 4608;
#pragma unroll
    for (int i = 0; i < 8; i++) {
      int idx = tid + i * 128;
      int kv = idx >> 4, d4 = (idx & 15) << 2;
      cp16(KsD + kv * 68 + d4, Kb + (long)kv * DM_ + d4);
      cp16(VsD + kv * 72 + d4, Vb + (long)kv * DM_ + d4);
    }
    cp_commit();
  };

  // Q A-fragments in registers for the whole KV loop
  unsigned qa[8][4];
  {
    int qrow = wid * 16 + g;
#pragma unroll
    for (int ks = 0; ks < 8; ks++) {
      int c = ks * 8 + tg;
      qa[ks][0] = f2tf(QSCALE * Qb[(long)qrow * DM_ + c]);
      qa[ks][1] = f2tf(QSCALE * Qb[(long)(qrow + 8) * DM_ + c]);
      qa[ks][2] = f2tf(QSCALE * Qb[(long)qrow * DM_ + c + 4]);
      qa[ks][3] = f2tf(QSCALE * Qb[(long)(qrow + 8) * DM_ + c + 4]);
    }
  }

  float oacc[8][4];
#pragma unroll
  for (int nt = 0; nt < 8; nt++)
#pragma unroll
    for (int j = 0; j < 4; j++) oacc[nt][j] = 0.f;
  float m0r = -INFINITY, m1r = -INFINITY, l0 = 0.f, l1 = 0.f;

  stage(0, 0);
  stage(1, 1);

  for (int kb = 0; kb < S_ / 64; kb++) {
    const int p = kb & 1;
    cp_wait1();
    __syncthreads();
    const unsigned* KsP = Ks + p * 4352;
    const unsigned* VsP = Vs + p * 4608;

    // ---- S = Q K^T ----
    float sacc[8][4];
#pragma unroll
    for (int nt = 0; nt < 8; nt++)
#pragma unroll
      for (int j = 0; j < 4; j++) sacc[nt][j] = 0.f;
#pragma unroll
    for (int nt = 0; nt < 8; nt++) {
#pragma unroll
      for (int ks = 0; ks < 8; ks++) {
        unsigned bf[2];
        int n  = nt * 8 + g;
        int kk = ks * 8 + tg;
        bf[0] = KsP[n * 68 + kk];
        bf[1] = KsP[n * 68 + kk + 4];
        mma_tf32(sacc[nt], qa[ks], bf);
      }
    }

    // ---- online softmax (exp2 domain) ----
    float mx0 = -INFINITY, mx1 = -INFINITY;
#pragma unroll
    for (int nt = 0; nt < 8; nt++) {
      mx0 = fmaxf(mx0, fmaxf(sacc[nt][0], sacc[nt][1]));
      mx1 = fmaxf(mx1, fmaxf(sacc[nt][2], sacc[nt][3]));
    }
#pragma unroll
    for (int off = 1; off <= 2; off <<= 1) {
      mx0 = fmaxf(mx0, __shfl_xor_sync(0xffffffffu, mx0, off));
      mx1 = fmaxf(mx1, __shfl_xor_sync(0xffffffffu, mx1, off));
    }
    float mn0 = fmaxf(m0r, mx0), mn1 = fmaxf(m1r, mx1);
    float al0 = exp2f(m0r - mn0), al1 = exp2f(m1r - mn1);
    m0r = mn0; m1r = mn1;

    float ps0 = 0.f, ps1 = 0.f;
#pragma unroll
    for (int nt = 0; nt < 8; nt++) {
      sacc[nt][0] = exp2f(sacc[nt][0] - mn0);
      sacc[nt][1] = exp2f(sacc[nt][1] - mn0);
      sacc[nt][2] = exp2f(sacc[nt][2] - mn1);
      sacc[nt][3] = exp2f(sacc[nt][3] - mn1);
      ps0 += sacc[nt][0] + sacc[nt][1];
      ps1 += sacc[nt][2] + sacc[nt][3];
    }
#pragma unroll
    for (int off = 1; off <= 2; off <<= 1) {
      ps0 += __shfl_xor_sync(0xffffffffu, ps0, off);
      ps1 += __shfl_xor_sync(0xffffffffu, ps1, off);
    }
    l0 = l0 * al0 + ps0;
    l1 = l1 * al1 + ps1;
#pragma unroll
    for (int nt = 0; nt < 8; nt++) {
      oacc[nt][0] *= al0;
      oacc[nt][1] *= al0;
      oacc[nt][2] *= al1;
      oacc[nt][3] *= al1;
    }

    // ---- store P (stride 68: conflict-free STS.32 and LDS.32) ----
    {
      int pr = wid * 16 + g;
#pragma unroll
      for (int nt = 0; nt < 8; nt++) {
        int col = nt * 8 + 2 * tg;
        Ps[pr * 68 + col]           = f2tf(sacc[nt][0]);
        Ps[pr * 68 + col + 1]       = f2tf(sacc[nt][1]);
        Ps[(pr + 8) * 68 + col]     = f2tf(sacc[nt][2]);
        Ps[(pr + 8) * 68 + col + 1] = f2tf(sacc[nt][3]);
      }
    }
    __syncwarp();

    // ---- O += P V ----
#pragma unroll
    for (int ks = 0; ks < 8; ks++) {
      unsigned pa[4];
      int pr  = wid * 16 + g;
      int col = ks * 8 + tg;
      pa[0] = Ps[pr * 68 + col];
      pa[1] = Ps[(pr + 8) * 68 + col];
      pa[2] = Ps[pr * 68 + col + 4];
      pa[3] = Ps[(pr + 8) * 68 + col + 4];
#pragma unroll
      for (int nt = 0; nt < 8; nt++) {
        unsigned bf[2];
        int n  = nt * 8 + g;
        int kk = ks * 8 + tg;
        bf[0] = VsP[kk * 72 + n];
        bf[1] = VsP[(kk + 4) * 72 + n];
        mma_tf32(oacc[nt], pa, bf);
      }
    }

    __syncthreads();
    if (kb + 2 < S_ / 64) stage(kb + 2, p);
    else cp_commit();
  }

  // epilogue: normalize, round to tf32 (final GEMM consumes raw)
  float inv0 = 1.f / l0, inv1 = 1.f / l1;
  int row = wid * 16 + g;
#pragma unroll
  for (int nt = 0; nt < 8; nt++) {
    int col = nt * 8 + 2 * tg;
    float2 o0 = make_float2(__uint_as_float(f2tf(oacc[nt][0] * inv0)),
                            __uint_as_float(f2tf(oacc[nt][1] * inv0)));
    float2 o1 = make_float2(__uint_as_float(f2tf(oacc[nt][2] * inv1)),
                            __uint_as_float(f2tf(oacc[nt][3] * inv1)));
    *(float2*)(Ob + (long)row * DM_ + col)       = o0;
    *(float2*)(Ob + (long)(row + 8) * DM_ + col) = o1;
  }
}

// ---------------------------------------------------------------------------
extern "C" void kernel_launch(void* const* d_in, const int* in_sizes, int n_in,
                              void* d_out, int out_size) {
  const float* x  = (const float*)d_in[0];
  const float* Wq = (const float*)d_in[1];
  const float* bq = (const float*)d_in[2];
  const float* Wk = (const float*)d_in[3];
  const float* bk = (const float*)d_in[4];
  const float* Wv = (const float*)d_in[5];
  const float* bv = (const float*)d_in[6];
  const float* Wo = (const float*)d_in[7];
  const float* bo = (const float*)d_in[8];
  float* out = (float*)d_out;

  float *q, *k, *v, *attn, *xt, *wq, *wk, *wv, *wo;
  cudaGetSymbolAddress((void**)&q, g_q);
  cudaGetSymbolAddress((void**)&k, g_k);
  cudaGetSymbolAddress((void**)&v, g_v);
  cudaGetSymbolAddress((void**)&attn, g_attn);
  cudaGetSymbolAddress((void**)&xt, g_xt);
  cudaGetSymbolAddress((void**)&wq, g_wq);
  cudaGetSymbolAddress((void**)&wk, g_wk);
  cudaGetSymbolAddress((void**)&wv, g_wv);
  cudaGetSymbolAddress((void**)&wo, g_wo);

  tf32_round_kernel<<<512, 256>>>(x, xt, (long)MROWS * DM_ / 4);
  tf32_round_kernel<<<128, 256>>>(Wq, wq, (long)DM_ * DM_ / 4);
  tf32_round_kernel<<<128, 256>>>(Wk, wk, (long)DM_ * DM_ / 4);
  tf32_round_kernel<<<128, 256>>>(Wv, wv, (long)DM_ * DM_ / 4);
  tf32_round_kernel<<<128, 256>>>(Wo, wo, (long)DM_ * DM_ / 4);

  dim3 qkvgrid(DM_ / 128, MROWS / 128, 3);
  gemm_qkv_kernel<<<qkvgrid, 256>>>(xt, wq, wk, wv, bq, bk, bv, q, k, v);

  const int flash_smem = (2 * 4352 + 2 * 4608 + 64 * 68) * (int)sizeof(unsigned);
  cudaFuncSetAttribute(flash_tc_kernel,
                       cudaFuncAttributeMaxDynamicSharedMemorySize, flash_smem);
  flash_tc_kernel<<<dim3(S_ / 64, B_ * H_), 128, flash_smem>>>(q, k, v, attn);

  dim3 ggrid(DM_ / 128, MROWS / 128);
  gemm_tc_kernel<<<ggrid, 256>>>(attn, wo, bo, out, 0);
}